// round 10
// baseline (speedup 1.0000x reference)
#include <cuda_runtime.h>
#include <cuda_fp16.h>
#include <cstdint>

#define Bsz 16384
#define Cn  8
#define Dd  256
#define H0n 512
#define H1n 256

// ---------------- scratch (device statics) ----------------
__device__ __align__(16) __half g_xh  [Bsz][Dd];           // 8MB   x fp16
__device__ __align__(16) __half g_w0h [Cn][H0n][Dd];       // 2MB   w0 fp16
__device__ __align__(16) __half g_w1h [Cn][H1n][H0n];      // 2MB   w1 fp16

// ---------------- prep: x, w0, w1 convert, one launch ----------------
__device__ __forceinline__ uint4 cvt8h(const float* s) {
    uint32_t h[4];
    #pragma unroll
    for (int i = 0; i < 4; i++) {
        __half h0 = __float2half_rn(s[2*i]), h1 = __float2half_rn(s[2*i+1]);
        h[i] = (uint32_t)__half_as_ushort(h0) | ((uint32_t)__half_as_ushort(h1) << 16);
    }
    return make_uint4(h[0], h[1], h[2], h[3]);
}

__global__ void prep_all(const float* __restrict__ x,
                         const float* __restrict__ W0, const float* __restrict__ W1) {
    int u = blockIdx.x * blockDim.x + threadIdx.x;   // 786432 total
    float buf[8];
    if (u < 524288) {                                 // x
        int k8 = u & 31, b = u >> 5;
        *(float4*)(buf)   = *(const float4*)(x + (size_t)b * Dd + k8 * 8);
        *(float4*)(buf+4) = *(const float4*)(x + (size_t)b * Dd + k8 * 8 + 4);
        *(uint4*)&g_xh[b][k8 * 8] = cvt8h(buf);
    } else if (u < 655360) {                          // w0
        int v = u - 524288;
        int k8 = v & 31, n = (v >> 5) & 511, c = v >> 14;
        const float* src = W0 + ((size_t)c * H0n + n) * Dd + k8 * 8;
        *(float4*)(buf)   = *(const float4*)(src);
        *(float4*)(buf+4) = *(const float4*)(src + 4);
        *(uint4*)&g_w0h[c][n][k8 * 8] = cvt8h(buf);
    } else {                                          // w1
        int v = u - 655360;
        int k8 = v & 63, n = (v >> 6) & 255, c = v >> 14;
        const float* src = W1 + ((size_t)c * H1n + n) * H0n + k8 * 8;
        *(float4*)(buf)   = *(const float4*)(src);
        *(float4*)(buf+4) = *(const float4*)(src + 4);
        *(uint4*)&g_w1h[c][n][k8 * 8] = cvt8h(buf);
    }
}

// ---------------- machinery ----------------
__device__ __forceinline__ uint32_t smem_u32(const void* p) {
    uint32_t a;
    asm("{ .reg .u64 t; cvta.to.shared.u64 t, %1; cvt.u32.u64 %0, t; }" : "=r"(a) : "l"(p));
    return a;
}
#define CP16(dst, src) asm volatile("cp.async.cg.shared.global [%0], [%1], 16;" :: "r"(dst), "l"(src))
#define CP_COMMIT()    asm volatile("cp.async.commit_group;" ::: "memory")
#define CP_WAIT0()     asm volatile("cp.async.wait_group 0;" ::: "memory")
#define LDSM4(r, a) \
    asm volatile("ldmatrix.sync.aligned.m8n8.x4.shared.b16 {%0,%1,%2,%3}, [%4];" \
        : "=r"((r)[0]), "=r"((r)[1]), "=r"((r)[2]), "=r"((r)[3]) : "r"(a))
#define MMA(d, a, b0, b1) \
    asm volatile("mma.sync.aligned.m16n8k16.row.col.f32.f16.f16.f32 " \
        "{%0,%1,%2,%3}, {%4,%5,%6,%7}, {%8,%9}, {%0,%1,%2,%3};" \
        : "+f"((d)[0]), "+f"((d)[1]), "+f"((d)[2]), "+f"((d)[3]) \
        : "r"((a)[0]), "r"((a)[1]), "r"((a)[2]), "r"((a)[3]), "r"(b0), "r"(b1))

// ---- smem layout (bytes) ----
// h0 tile:  [0, 131072)        128 rows x 1024B (512 fp16), XOR-swizzled rows
// ring:     [131072, 196608)   2 stages x 32KB; stage: A 16KB @ +0, B 16KB @ +16384
// aux:      b0s 2KB | b1s 1KB | w2s 1KB | red 2KB
#define H0S    0
#define RING   131072
#define STG    32768
#define B0OFF  196608
#define B1OFF  198656
#define W2OFF  199680
#define REDOFF 200704
#define SMEM_TOTAL 202752

// ============ fused: h0 = relu(x@w0^T+b0) in smem; out = relu(h0@w1^T+b1).w2 + b2 ============
__global__ void __launch_bounds__(512, 1)
fused(const float* __restrict__ b0g, const float* __restrict__ b1g,
      const float* __restrict__ w2g, const float* __restrict__ b2g,
      float* __restrict__ out)
{
    extern __shared__ __align__(128) uint8_t sm[];
    const uint32_t sb = smem_u32(sm);
    const int tid = threadIdx.x, lane = tid & 31, wid = tid >> 5;
    const int wm0 = (wid & 3) * 32, wn0 = (wid >> 2) * 32;   // warp tile 32x32 over 128x128
    const int m0 = blockIdx.x * 128, c = blockIdx.y;
    const int prow = tid >> 3, pg = tid & 7;                  // prow 0..63
    const uint32_t pdst = sb + RING + prow * 128 + ((pg ^ (prow & 7)) << 4);

    float* b0s = (float*)(sm + B0OFF);
    float* b1s = (float*)(sm + B1OFF);
    float* w2s = (float*)(sm + W2OFF);
    float* red = (float*)(sm + REDOFF);
    if (tid < 512) b0s[tid] = b0g[c * H0n + tid];
    if (tid >= 512 - 256) { }  // (kept simple below)
    if (tid < 256) { b1s[tid] = b1g[c * H1n + tid]; w2s[tid] = w2g[c * H1n + tid]; }

// L0 produce: step 0..15 (nc = step>>2, t = step&3); A 16KB + B 16KB
#define PRODUCE_L0(s, step) do {                                               \
    const int _t = (step) & 3, _nc = (step) >> 2;                              \
    _Pragma("unroll")                                                          \
    for (int i = 0; i < 2; i++) {                                              \
        int row = prow + i * 64;                                               \
        CP16(pdst + (s) * STG + i * 8192,                                      \
             &g_xh[m0 + row][_t * 64 + pg * 8]);                               \
        CP16(pdst + (s) * STG + 16384 + i * 8192,                              \
             &g_w0h[c][_nc * 128 + row][_t * 64 + pg * 8]);                    \
    }                                                                          \
} while (0)

// L1 produce: B only, step 0..15 (nc = step>>3, u = step&7)
#define PRODUCE_L1(s, step) do {                                               \
    const int _u = (step) & 7, _nc = (step) >> 3;                              \
    _Pragma("unroll")                                                          \
    for (int i = 0; i < 2; i++) {                                              \
        int row = prow + i * 64;                                               \
        CP16(pdst + (s) * STG + 16384 + i * 8192,                              \
             &g_w1h[c][_nc * 128 + row][_u * 64 + pg * 8]);                    \
    }                                                                          \
} while (0)

#define LOADB(sB) do {                                                         \
    _Pragma("unroll")                                                          \
    for (int ng = 0; ng < 2; ng++) {                                           \
        int row = wn0 + ng * 16 + (lane & 7) + ((lane >> 4) << 3);             \
        int g   = s16 * 2 + ((lane >> 3) & 1);                                 \
        LDSM4(bfr[ng], (sB) + row * 128 + ((g ^ (row & 7)) << 4));             \
    }                                                                          \
} while (0)

#define DOMMA() \
    _Pragma("unroll")                                                          \
    for (int mt = 0; mt < 2; mt++)                                             \
        _Pragma("unroll")                                                      \
        for (int ni = 0; ni < 4; ni++)                                         \
            MMA(acc[mt][ni], afr[mt], bfr[ni >> 1][(ni & 1) * 2],              \
                bfr[ni >> 1][(ni & 1) * 2 + 1])

#define ACC_ZERO()                                                             \
    _Pragma("unroll")                                                          \
    for (int a = 0; a < 2; a++)                                                \
        _Pragma("unroll")                                                      \
        for (int b = 0; b < 4; b++)                                            \
            _Pragma("unroll")                                                  \
            for (int r = 0; r < 4; r++) acc[a][b][r] = 0.0f;

    float acc[2][4][4];
    ACC_ZERO();

    // =================== Layer 0 ===================
    PRODUCE_L0(0, 0); CP_COMMIT();

    #pragma unroll 1
    for (int s = 0; s < 16; s++) {
        CP_WAIT0();
        __syncthreads();
        if (s < 15) { PRODUCE_L0((s + 1) & 1, s + 1); }
        else        { PRODUCE_L1((s + 1) & 1, 0); }      // prefetch L1 step 0
        CP_COMMIT();
        const uint32_t sA = sb + RING + (s & 1) * STG;
        const uint32_t sB = sA + 16384;
        #pragma unroll
        for (int s16 = 0; s16 < 4; s16++) {
            uint32_t afr[2][4], bfr[2][4];
            #pragma unroll
            for (int mt = 0; mt < 2; mt++) {
                int row = wm0 + mt * 16 + (lane & 7) + ((lane >> 3) & 1) * 8;
                int g   = s16 * 2 + (lane >> 4);
                LDSM4(afr[mt], sA + row * 128 + ((g ^ (row & 7)) << 4));
            }
            LOADB(sB);
            DOMMA();
        }

        if ((s & 3) == 3) {
            // epilogue for n-chunk (s>>2): relu(+b0) -> fp16 -> smem h0 tile
            const int nc = s >> 2;
            #pragma unroll
            for (int mt = 0; mt < 2; mt++) {
                #pragma unroll
                for (int ni = 0; ni < 4; ni++) {
                    const int n = nc * 128 + wn0 + ni * 8 + (lane & 3) * 2;
                    const float bn0 = b0s[n], bn1 = b0s[n + 1];
                    #pragma unroll
                    for (int half = 0; half < 2; half++) {
                        const int m = wm0 + mt * 16 + (lane >> 2) + half * 8;
                        float v0 = fmaxf(acc[mt][ni][half * 2 + 0] + bn0, 0.0f);
                        float v1 = fmaxf(acc[mt][ni][half * 2 + 1] + bn1, 0.0f);
                        __half h0 = __float2half_rn(v0), h1 = __float2half_rn(v1);
                        uint32_t hp = (uint32_t)__half_as_ushort(h0)
                                    | ((uint32_t)__half_as_ushort(h1) << 16);
                        *(uint32_t*)(sm + H0S + m * 1024 + ((2 * n) ^ ((m & 7) << 4))) = hp;
                    }
                }
            }
            ACC_ZERO();
        }
    }

    // =================== Layer 1 ===================
    float sacc[4];
    #pragma unroll
    for (int i = 0; i < 4; i++) sacc[i] = 0.0f;

    #pragma unroll 1
    for (int u = 0; u < 16; u++) {
        CP_WAIT0();
        __syncthreads();          // step 0: also orders h0 writes before LDSM reads
        if (u < 15) { PRODUCE_L1((u + 1) & 1, u + 1); }
        CP_COMMIT();
        const uint32_t sB = sb + RING + (u & 1) * STG + 16384;
        const int kq = u & 7;     // k64 index within this n-chunk
        #pragma unroll
        for (int s16 = 0; s16 < 4; s16++) {
            uint32_t afr[2][4], bfr[2][4];
            const int kg = kq * 4 + s16;          // k16-group 0..31
            #pragma unroll
            for (int mt = 0; mt < 2; mt++) {
                int row = wm0 + mt * 16 + (lane & 7) + ((lane >> 3) & 1) * 8;
                int g   = kg * 2 + (lane >> 4);   // 16B unit 0..63
                LDSM4(afr[mt], sb + H0S + row * 1024 + (((uint32_t)g << 4) ^ ((row & 7) << 4)));
            }
            LOADB(sB);
            DOMMA();
        }

        if ((u & 7) == 7) {
            // fold this n-chunk into head dot: relu(+b1).w2
            const int nc = u >> 3;
            #pragma unroll
            for (int mt = 0; mt < 2; mt++) {
                #pragma unroll
                for (int ni = 0; ni < 4; ni++) {
                    const int n = nc * 128 + wn0 + ni * 8 + (lane & 3) * 2;
                    const float bn0 = b1s[n],  bn1 = b1s[n + 1];
                    const float w0v = w2s[n],  w1v = w2s[n + 1];
                    sacc[mt * 2 + 0] += fmaxf(acc[mt][ni][0] + bn0, 0.0f) * w0v
                                      + fmaxf(acc[mt][ni][1] + bn1, 0.0f) * w1v;
                    sacc[mt * 2 + 1] += fmaxf(acc[mt][ni][2] + bn0, 0.0f) * w0v
                                      + fmaxf(acc[mt][ni][3] + bn1, 0.0f) * w1v;
                }
            }
            ACC_ZERO();
        }
    }

    // =================== final reduce: quad lanes, then 4 n-warp-groups ===================
    #pragma unroll
    for (int i = 0; i < 4; i++) {
        sacc[i] += __shfl_xor_sync(0xFFFFFFFF, sacc[i], 1);
        sacc[i] += __shfl_xor_sync(0xFFFFFFFF, sacc[i], 2);
    }
    __syncthreads();
    if ((lane & 3) == 0) {
        #pragma unroll
        for (int mt = 0; mt < 2; mt++)
            #pragma unroll
            for (int half = 0; half < 2; half++) {
                int r = wm0 + mt * 16 + half * 8 + (lane >> 2);
                red[r * 4 + (wid >> 2)] = sacc[mt * 2 + half];
            }
    }
    __syncthreads();
    if (tid < 128) {
        float v = red[tid * 4] + red[tid * 4 + 1] + red[tid * 4 + 2] + red[tid * 4 + 3];
        out[(size_t)(m0 + tid) * Cn + c] = v + b2g[c];
    }
}

extern "C" void kernel_launch(void* const* d_in, const int* in_sizes, int n_in,
                              void* d_out, int out_size) {
    (void)in_sizes; (void)n_in; (void)out_size;
    const float* x  = (const float*)d_in[0];
    const float* W0 = (const float*)d_in[1];
    const float* b0 = (const float*)d_in[2];
    const float* W1 = (const float*)d_in[3];
    const float* b1 = (const float*)d_in[4];
    const float* W2 = (const float*)d_in[5];
    const float* b2 = (const float*)d_in[6];
    float* out = (float*)d_out;

    prep_all<<<3072, 256>>>(x, W0, W1);

    cudaFuncSetAttribute(fused, cudaFuncAttributeMaxDynamicSharedMemorySize, SMEM_TOTAL);
    fused<<<dim3(128, 8), 512, SMEM_TOTAL>>>(b0, b1, W2, b2, out);
}